// round 4
// baseline (speedup 1.0000x reference)
#include <cuda_runtime.h>
#include <cstdint>

// Problem constants (fixed shapes)
#define Bc 16
#define Cc 3
#define Hc 1024
#define Wc 1024
#define NF 15728
#define WW (Wc / 32)          // 32 bit-words per row

// 2 MB per-(b,y,x) flake BITmask scratch (device global: allocation-guard safe)
__device__ uint32_t g_bits[(size_t)Bc * Hc * WW];

// ---------------------------------------------------------------------------
// 1) clear bitmask: 2 MB of zeros, vectorized 16B stores
// ---------------------------------------------------------------------------
__global__ void hs_clear_mask() {
    size_t i = (size_t)blockIdx.x * blockDim.x + threadIdx.x;
    reinterpret_cast<uint4*>(g_bits)[i] = make_uint4(0u, 0u, 0u, 0u);
}

// ---------------------------------------------------------------------------
// 2) stamp flakes: one THREAD per flake; each of the <=7 rows becomes 1-2
//    atomicOr (REDG) into the L2-resident bitmask. OOB rows/cols are clipped
//    (equivalent to reference's clamp-to-border: the clamped pixel is always
//    covered by an in-range offset).
// ---------------------------------------------------------------------------
__global__ void hs_stamp(const int* __restrict__ ys,
                         const int* __restrict__ xs,
                         const int* __restrict__ rs) {
    int idx = blockIdx.x * blockDim.x + threadIdx.x;
    if (idx >= Bc * NF) return;
    int b  = idx / NF;
    int cy = ys[idx];
    int cx = xs[idx];
    int r  = rs[idx];

    int x0 = max(cx - r, 0);
    int x1 = min(cx + r, Wc - 1);
    int w0 = x0 >> 5;
    uint64_t m  = ((1ull << (x1 - x0 + 1)) - 1ull) << (x0 & 31);
    uint32_t lo = (uint32_t)m;
    uint32_t hi = (uint32_t)(m >> 32);

    uint32_t* bb = g_bits + (size_t)b * Hc * WW;
    #pragma unroll
    for (int dy = -3; dy <= 3; dy++) {
        if (dy < -r || dy > r) continue;
        int y = cy + dy;
        if ((unsigned)y >= Hc) continue;
        uint32_t* row = bb + (size_t)y * WW;
        atomicOr(&row[w0], lo);
        if (hi) atomicOr(&row[w0 + 1], hi);
    }
}

// ---------------------------------------------------------------------------
// 3) fused composite + separable 5x5 gaussian blur + clip
//    Tile: 128 x 64 outputs per block, 128 threads = 4 strips x 32 lanes.
//    Each strip owns 16 output rows (horizontal recompute 20/16 = 1.25x).
//    Conflict-free LDS.128 horizontal pass, register-ring vertical pass.
//    All blur math as FFMA-imm chains (rt_SMSP=1), saturate folded at the end.
// ---------------------------------------------------------------------------
#define TX 128
#define TY 64
#define NSTRIP 4
#define RS 16      // output rows per strip
#define SW 136     // staged width  (gx0-4 .. gx0+131), 16B aligned rows
#define SH 68      // staged height (gy0-2 .. gy0+65)
#define NTHR 128

// Gaussian weights: g = exp(-c^2/(2*1.5^2)), c in [-2..2], normalized.
#define W0 0.12007829f
#define W1 0.23388140f
#define W2 0.29208061f

// 5-tap as FFMA-imm chain: a*W0 + b*W1 + c*W2 + d*W1 + e*W0
__device__ __forceinline__ float tap5(float a, float b, float c, float d, float e) {
    return fmaf(a, W0, fmaf(e, W0, fmaf(b, W1, fmaf(d, W1, c * W2))));
}

__global__ __launch_bounds__(NTHR) void hs_blur(const float* __restrict__ xin,
                                                float* __restrict__ out) {
    __shared__ float s_in[SH][SW];

    const int gx0 = blockIdx.x * TX;
    const int gy0 = blockIdx.y * TY;
    const int z   = blockIdx.z;          // b*C + c
    const int b   = z / Cc;
    const float*    xp = xin + (size_t)z * Hc * Wc;
    const uint32_t* bp = g_bits + (size_t)b * Hc * WW;
    const int tid = threadIdx.x;

    // -- load + composite (zero pad outside image) --
    // SW/4 = 34 float4 per row, SH = 68 rows -> 2312 float4 tasks, 128 thr
    #pragma unroll
    for (int i = 0; i < 19; i++) {
        int idx = tid + i * NTHR;
        if (idx < 34 * SH) {
            int row = idx / 34;
            int c4  = idx - row * 34;
            int gy  = gy0 - 2 + row;
            int gxa = gx0 - 4 + c4 * 4;
            float4 v = make_float4(0.f, 0.f, 0.f, 0.f);
            if ((unsigned)gy < Hc && (unsigned)gxa < Wc) {
                v = __ldcs(reinterpret_cast<const float4*>(
                        xp + (size_t)gy * Wc + gxa));
                uint32_t w = bp[(size_t)gy * WW + (gxa >> 5)];
                if (w) {
                    uint32_t nib = (w >> (gxa & 31)) & 0xFu;
                    if (nib & 1u) v.x = 0.95f;
                    if (nib & 2u) v.y = 0.95f;
                    if (nib & 4u) v.z = 0.95f;
                    if (nib & 8u) v.w = 0.95f;
                }
            }
            *reinterpret_cast<float4*>(&s_in[row][c4 * 4]) = v;
        }
    }
    __syncthreads();

    const int lane  = tid & 31;
    const int strip = tid >> 5;          // 0..3
    const int row0  = strip * RS;        // s_in row for t=0 (= out row - 2)
    float* obase = out + (size_t)z * Hc * Wc
                 + (size_t)(gy0 + strip * RS) * Wc + gx0 + 4 * lane;

    float4 h[5];
    #pragma unroll
    for (int t = 0; t < RS + 4; t++) {
        // horizontal pass for s_in row (row0 + t): 3 aligned LDS.128
        const float* p = &s_in[row0 + t][4 * lane];
        float4 A  = *reinterpret_cast<const float4*>(p);
        float4 Bv = *reinterpret_cast<const float4*>(p + 4);
        float4 Cv = *reinterpret_cast<const float4*>(p + 8);
        float4 hv;
        hv.x = tap5(A.z,  A.w,  Bv.x, Bv.y, Bv.z);
        hv.y = tap5(A.w,  Bv.x, Bv.y, Bv.z, Bv.w);
        hv.z = tap5(Bv.x, Bv.y, Bv.z, Bv.w, Cv.x);
        hv.w = tap5(Bv.y, Bv.z, Bv.w, Cv.x, Cv.y);
        h[t % 5] = hv;

        if (t >= 4) {
            // vertical pass for output row (t-4) of this strip
            float4 a = h[(t - 4) % 5], bb2 = h[(t - 3) % 5], c = h[(t - 2) % 5];
            float4 d = h[(t - 1) % 5], e = h[t % 5];
            float4 o;
            o.x = __saturatef(tap5(a.x, bb2.x, c.x, d.x, e.x));
            o.y = __saturatef(tap5(a.y, bb2.y, c.y, d.y, e.y));
            o.z = __saturatef(tap5(a.z, bb2.z, c.z, d.z, e.z));
            o.w = __saturatef(tap5(a.w, bb2.w, c.w, d.w, e.w));
            __stcs(reinterpret_cast<float4*>(obase + (size_t)(t - 4) * Wc), o);
        }
    }
}

// ---------------------------------------------------------------------------
extern "C" void kernel_launch(void* const* d_in, const int* in_sizes, int n_in,
                              void* d_out, int out_size) {
    const float* x  = (const float*)d_in[0];
    const int*   ys = (const int*)d_in[1];
    const int*   xs = (const int*)d_in[2];
    const int*   rs = (const int*)d_in[3];
    float* out = (float*)d_out;

    // 1) clear bitmask: 2 MB / 16B = 131,072 uint4 stores
    hs_clear_mask<<<512, 256>>>();

    // 2) stamp: thread per flake
    int total_flakes = Bc * NF;                 // 251,648
    hs_stamp<<<(total_flakes + 255) / 256, 256>>>(ys, xs, rs);

    // 3) fused composite + blur + clip
    dim3 grid(Wc / TX, Hc / TY, Bc * Cc);       // (8, 16, 48)
    hs_blur<<<grid, NTHR>>>(x, out);
}

// round 5
// speedup vs baseline: 1.1115x; 1.1115x over previous
#include <cuda_runtime.h>
#include <cstdint>

// Problem constants (fixed shapes)
#define Bc 16
#define Cc 3
#define Hc 1024
#define Wc 1024
#define NF 15728
#define WW (Wc / 32)          // 32 bit-words per row

// 2 MB per-(b,y,x) flake BITmask scratch (device global: allocation-guard safe)
__device__ uint32_t g_bits[(size_t)Bc * Hc * WW];

// ---------------------------------------------------------------------------
// 1) clear bitmask: 2 MB of zeros, vectorized 16B stores
// ---------------------------------------------------------------------------
__global__ void hs_clear_mask() {
    size_t i = (size_t)blockIdx.x * blockDim.x + threadIdx.x;
    reinterpret_cast<uint4*>(g_bits)[i] = make_uint4(0u, 0u, 0u, 0u);
}

// ---------------------------------------------------------------------------
// 2) stamp flakes: one THREAD per flake; each of the <=7 rows becomes 1-2
//    atomicOr (REDG) into the L2-resident bitmask. OOB rows/cols are clipped
//    (equivalent to reference's clamp-to-border: the clamped pixel is always
//    covered by an in-range offset).
// ---------------------------------------------------------------------------
__global__ void hs_stamp(const int* __restrict__ ys,
                         const int* __restrict__ xs,
                         const int* __restrict__ rs) {
    int idx = blockIdx.x * blockDim.x + threadIdx.x;
    if (idx >= Bc * NF) return;
    int b  = idx / NF;
    int cy = ys[idx];
    int cx = xs[idx];
    int r  = rs[idx];

    int x0 = max(cx - r, 0);
    int x1 = min(cx + r, Wc - 1);
    int w0 = x0 >> 5;
    uint64_t m  = ((1ull << (x1 - x0 + 1)) - 1ull) << (x0 & 31);
    uint32_t lo = (uint32_t)m;
    uint32_t hi = (uint32_t)(m >> 32);

    uint32_t* bb = g_bits + (size_t)b * Hc * WW;
    #pragma unroll
    for (int dy = -3; dy <= 3; dy++) {
        if (dy < -r || dy > r) continue;
        int y = cy + dy;
        if ((unsigned)y >= Hc) continue;
        uint32_t* row = bb + (size_t)y * WW;
        atomicOr(&row[w0], lo);
        if (hi) atomicOr(&row[w0 + 1], hi);
    }
}

// ---------------------------------------------------------------------------
// 3) fused composite + separable 5x5 gaussian blur + clip
//    Tile: 128 x 64 outputs per block, 256 threads = 8 strips x 32 lanes.
//    Conflict-free LDS.128 horizontal pass, register-ring vertical pass.
//    FFMA-imm chains; interior tiles take an unconditional batched-load path.
// ---------------------------------------------------------------------------
#define TX 128
#define TY 64
#define RS 8       // output rows per strip
#define SW 136     // staged width  (gx0-4 .. gx0+131), 16B aligned rows
#define SH 68      // staged height (gy0-2 .. gy0+65)
#define NTHR 256

// Gaussian weights: g = exp(-c^2/(2*1.5^2)), c in [-2..2], normalized.
#define W0 0.12007829f
#define W1 0.23388140f
#define W2 0.29208061f

// 5-tap as FFMA-imm chain
__device__ __forceinline__ float tap5(float a, float b, float c, float d, float e) {
    return fmaf(a, W0, fmaf(e, W0, fmaf(b, W1, fmaf(d, W1, c * W2))));
}

__device__ __forceinline__ void composite4(float4& v, uint32_t w, int sh) {
    uint32_t nib = (w >> sh) & 0xFu;
    if (nib) {
        if (nib & 1u) v.x = 0.95f;
        if (nib & 2u) v.y = 0.95f;
        if (nib & 4u) v.z = 0.95f;
        if (nib & 8u) v.w = 0.95f;
    }
}

__global__ __launch_bounds__(NTHR) void hs_blur(const float* __restrict__ xin,
                                                float* __restrict__ out) {
    __shared__ float s_in[SH][SW];

    const int gx0 = blockIdx.x * TX;
    const int gy0 = blockIdx.y * TY;
    const int z   = blockIdx.z;          // b*C + c
    const int b   = z / Cc;
    const float*    xp = xin + (size_t)z * Hc * Wc;
    const uint32_t* bp = g_bits + (size_t)b * Hc * WW;
    const int tid = threadIdx.x;

    const bool interior = (blockIdx.x > 0) & (blockIdx.x < 7) &
                          (blockIdx.y > 0) & (blockIdx.y < 15);

    if (interior) {
        // Unconditional batched loads: 2312 float4 tasks over 256 threads.
        // First 9 iterations fully active; 8 leftover tasks in iteration 9.
        int row = tid / 34 * 1;          // recomputed per iter below
        #pragma unroll
        for (int i = 0; i < 9; i++) {
            int idx = tid + i * NTHR;
            int r_  = idx / 34;
            int c4  = idx - r_ * 34;
            int gy  = gy0 - 2 + r_;
            int gxa = gx0 - 4 + c4 * 4;
            float4 v = __ldcs(reinterpret_cast<const float4*>(
                    xp + (size_t)gy * Wc + gxa));
            uint32_t w = __ldg(&bp[(size_t)gy * WW + (gxa >> 5)]);
            composite4(v, w, gxa & 31);
            *reinterpret_cast<float4*>(&s_in[r_][c4 * 4]) = v;
        }
        {
            int idx = tid + 9 * NTHR;
            if (idx < 34 * SH) {
                int r_  = idx / 34;
                int c4  = idx - r_ * 34;
                int gy  = gy0 - 2 + r_;
                int gxa = gx0 - 4 + c4 * 4;
                float4 v = __ldcs(reinterpret_cast<const float4*>(
                        xp + (size_t)gy * Wc + gxa));
                uint32_t w = __ldg(&bp[(size_t)gy * WW + (gxa >> 5)]);
                composite4(v, w, gxa & 31);
                *reinterpret_cast<float4*>(&s_in[r_][c4 * 4]) = v;
            }
        }
        (void)row;
    } else {
        #pragma unroll
        for (int i = 0; i < 10; i++) {
            int idx = tid + i * NTHR;
            if (idx < 34 * SH) {
                int r_  = idx / 34;
                int c4  = idx - r_ * 34;
                int gy  = gy0 - 2 + r_;
                int gxa = gx0 - 4 + c4 * 4;
                float4 v = make_float4(0.f, 0.f, 0.f, 0.f);
                if ((unsigned)gy < Hc && (unsigned)gxa < Wc) {
                    v = __ldcs(reinterpret_cast<const float4*>(
                            xp + (size_t)gy * Wc + gxa));
                    uint32_t w = __ldg(&bp[(size_t)gy * WW + (gxa >> 5)]);
                    composite4(v, w, gxa & 31);
                }
                *reinterpret_cast<float4*>(&s_in[r_][c4 * 4]) = v;
            }
        }
    }
    __syncthreads();

    const int lane  = tid & 31;
    const int strip = tid >> 5;          // 0..7
    const int row0  = strip * RS;        // s_in row for t=0 (= out row - 2)
    float* obase = out + (size_t)z * Hc * Wc
                 + (size_t)(gy0 + strip * RS) * Wc + gx0 + 4 * lane;

    float4 h[5];
    #pragma unroll
    for (int t = 0; t < RS + 4; t++) {
        // horizontal pass for s_in row (row0 + t): 3 aligned LDS.128
        const float* p = &s_in[row0 + t][4 * lane];
        float4 A  = *reinterpret_cast<const float4*>(p);
        float4 Bv = *reinterpret_cast<const float4*>(p + 4);
        float4 Cv = *reinterpret_cast<const float4*>(p + 8);
        float4 hv;
        hv.x = tap5(A.z,  A.w,  Bv.x, Bv.y, Bv.z);
        hv.y = tap5(A.w,  Bv.x, Bv.y, Bv.z, Bv.w);
        hv.z = tap5(Bv.x, Bv.y, Bv.z, Bv.w, Cv.x);
        hv.w = tap5(Bv.y, Bv.z, Bv.w, Cv.x, Cv.y);
        h[t % 5] = hv;

        if (t >= 4) {
            // vertical pass for output row (t-4) of this strip
            float4 a = h[(t - 4) % 5], bb2 = h[(t - 3) % 5], c = h[(t - 2) % 5];
            float4 d = h[(t - 1) % 5], e = h[t % 5];
            float4 o;
            o.x = __saturatef(tap5(a.x, bb2.x, c.x, d.x, e.x));
            o.y = __saturatef(tap5(a.y, bb2.y, c.y, d.y, e.y));
            o.z = __saturatef(tap5(a.z, bb2.z, c.z, d.z, e.z));
            o.w = __saturatef(tap5(a.w, bb2.w, c.w, d.w, e.w));
            __stcs(reinterpret_cast<float4*>(obase + (size_t)(t - 4) * Wc), o);
        }
    }
}

// ---------------------------------------------------------------------------
extern "C" void kernel_launch(void* const* d_in, const int* in_sizes, int n_in,
                              void* d_out, int out_size) {
    const float* x  = (const float*)d_in[0];
    const int*   ys = (const int*)d_in[1];
    const int*   xs = (const int*)d_in[2];
    const int*   rs = (const int*)d_in[3];
    float* out = (float*)d_out;

    // 1) clear bitmask: 2 MB / 16B = 131,072 uint4 stores
    hs_clear_mask<<<512, 256>>>();

    // 2) stamp: thread per flake
    int total_flakes = Bc * NF;                 // 251,648
    hs_stamp<<<(total_flakes + 255) / 256, 256>>>(ys, xs, rs);

    // 3) fused composite + blur + clip
    dim3 grid(Wc / TX, Hc / TY, Bc * Cc);       // (8, 16, 48)
    hs_blur<<<grid, NTHR>>>(x, out);
}

// round 6
// speedup vs baseline: 1.2764x; 1.1484x over previous
#include <cuda_runtime.h>
#include <cstdint>

// Problem constants (fixed shapes)
#define Bc 16
#define Cc 3
#define Hc 1024
#define Wc 1024
#define NF 15728
#define WW (Wc / 32)          // 32 bit-words per row

// 2 MB per-(b,y,x) flake BITmask scratch (device global: allocation-guard safe)
__device__ uint32_t g_bits[(size_t)Bc * Hc * WW];

// ---------------------------------------------------------------------------
// 1) clear bitmask: 2 MB of zeros, vectorized 16B stores
// ---------------------------------------------------------------------------
__global__ void hs_clear_mask() {
    size_t i = (size_t)blockIdx.x * blockDim.x + threadIdx.x;
    reinterpret_cast<uint4*>(g_bits)[i] = make_uint4(0u, 0u, 0u, 0u);
}

// ---------------------------------------------------------------------------
// 2) stamp flakes: one THREAD per flake; each of the <=7 rows becomes 1-2
//    atomicOr (REDG) into the L2-resident bitmask. OOB rows/cols are clipped
//    (equivalent to reference's clamp-to-border: the clamped pixel is always
//    covered by an in-range offset).
// ---------------------------------------------------------------------------
__global__ void hs_stamp(const int* __restrict__ ys,
                         const int* __restrict__ xs,
                         const int* __restrict__ rs) {
    int idx = blockIdx.x * blockDim.x + threadIdx.x;
    if (idx >= Bc * NF) return;
    int b  = idx / NF;
    int cy = ys[idx];
    int cx = xs[idx];
    int r  = rs[idx];

    int x0 = max(cx - r, 0);
    int x1 = min(cx + r, Wc - 1);
    int w0 = x0 >> 5;
    uint64_t m  = ((1ull << (x1 - x0 + 1)) - 1ull) << (x0 & 31);
    uint32_t lo = (uint32_t)m;
    uint32_t hi = (uint32_t)(m >> 32);

    uint32_t* bb = g_bits + (size_t)b * Hc * WW;
    #pragma unroll
    for (int dy = -3; dy <= 3; dy++) {
        if (dy < -r || dy > r) continue;
        int y = cy + dy;
        if ((unsigned)y >= Hc) continue;
        uint32_t* row = bb + (size_t)y * WW;
        atomicOr(&row[w0], lo);
        if (hi) atomicOr(&row[w0 + 1], hi);
    }
}

// ---------------------------------------------------------------------------
// 3) fused composite + separable 5x5 gaussian blur + clip
//    Tile: 128 x 64 outputs, 256 threads.
//    Load phase: warp per staged row; horizontal blur computed AT LOAD TIME
//    using 4 warp shuffles for the +-2 halo (edge lanes: predicated extra
//    LDG); only the h-blurred row is staged (s_h[68][128]).
//    Compute phase: vertical-only, 12 conflict-free LDS.128 per 8 outputs,
//    register ring, streaming STG.128.
// ---------------------------------------------------------------------------
#define TX 128
#define TY 64
#define RS 8       // output rows per strip
#define SH 68      // staged rows (gy0-2 .. gy0+65)
#define NTHR 256

// Gaussian weights: g = exp(-c^2/(2*1.5^2)), c in [-2..2], normalized.
#define W0 0.12007829f
#define W1 0.23388140f
#define W2 0.29208061f

// 5-tap as FFMA-imm chain
__device__ __forceinline__ float tap5(float a, float b, float c, float d, float e) {
    return fmaf(a, W0, fmaf(e, W0, fmaf(b, W1, fmaf(d, W1, c * W2))));
}

__global__ __launch_bounds__(NTHR) void hs_blur(const float* __restrict__ xin,
                                                float* __restrict__ out) {
    __shared__ float s_h[SH][TX];

    const int gx0 = blockIdx.x * TX;
    const int gy0 = blockIdx.y * TY;
    const int z   = blockIdx.z;          // b*C + c
    const int b   = z / Cc;
    const float*    xp = xin + (size_t)z * Hc * Wc;
    const uint32_t* bp = g_bits + (size_t)b * Hc * WW;
    const int tid  = threadIdx.x;
    const int lane = tid & 31;
    const int wid  = tid >> 5;           // 0..7

    const bool hasL = (gx0 > 0);
    const bool hasR = (gx0 + TX < Wc);

    // ---- load + composite + horizontal blur: warp per row ----
    #pragma unroll
    for (int it = 0; it < 9; it++) {
        int rr = wid + it * 8;
        if (rr < SH) {
            int gy = gy0 - 2 + rr;
            bool rowOK = (unsigned)gy < Hc;
            float4 v = make_float4(0.f, 0.f, 0.f, 0.f);
            float eLz = 0.f, eLw = 0.f, eRx = 0.f, eRy = 0.f;
            if (rowOK) {
                const float*    rowp = xp + (size_t)gy * Wc;
                const uint32_t* mrow = bp + (size_t)gy * WW;
                v = __ldcs(reinterpret_cast<const float4*>(rowp + gx0 + 4 * lane));
                uint32_t w = __ldg(&mrow[(gx0 >> 5) + (lane >> 3)]);
                uint32_t nib = (w >> (4 * (lane & 7))) & 0xFu;
                if (nib & 1u) v.x = 0.95f;
                if (nib & 2u) v.y = 0.95f;
                if (nib & 4u) v.z = 0.95f;
                if (nib & 8u) v.w = 0.95f;
                if (lane == 0 && hasL) {
                    float4 t = __ldcs(reinterpret_cast<const float4*>(rowp + gx0 - 4));
                    uint32_t mw = __ldg(&mrow[(gx0 - 4) >> 5]);
                    eLz = (mw & (1u << 30)) ? 0.95f : t.z;   // in[gx0-2]
                    eLw = (mw & (1u << 31)) ? 0.95f : t.w;   // in[gx0-1]
                }
                if (lane == 31 && hasR) {
                    float4 t = __ldcs(reinterpret_cast<const float4*>(rowp + gx0 + TX));
                    uint32_t mw = __ldg(&mrow[(gx0 + TX) >> 5]);
                    eRx = (mw & 1u) ? 0.95f : t.x;           // in[gx0+128]
                    eRy = (mw & 2u) ? 0.95f : t.y;           // in[gx0+129]
                }
            }
            // halo exchange: p[-2],p[-1] from lane-1; p[4],p[5] from lane+1
            float a = __shfl_up_sync(0xFFFFFFFFu, v.z, 1);
            float bb2 = __shfl_up_sync(0xFFFFFFFFu, v.w, 1);
            float c = __shfl_down_sync(0xFFFFFFFFu, v.x, 1);
            float d = __shfl_down_sync(0xFFFFFFFFu, v.y, 1);
            if (lane == 0)  { a = eLz; bb2 = eLw; }
            if (lane == 31) { c = eRx; d = eRy; }
            float4 hv;
            hv.x = tap5(a,   bb2, v.x, v.y, v.z);
            hv.y = tap5(bb2, v.x, v.y, v.z, v.w);
            hv.z = tap5(v.x, v.y, v.z, v.w, c);
            hv.w = tap5(v.y, v.z, v.w, c,   d);
            *reinterpret_cast<float4*>(&s_h[rr][4 * lane]) = hv;
        }
    }
    __syncthreads();

    // ---- vertical pass: strip (wid) owns 8 output rows ----
    float* obase = out + (size_t)z * Hc * Wc
                 + (size_t)(gy0 + wid * RS) * Wc + gx0 + 4 * lane;
    float4 h[5];
    #pragma unroll
    for (int t = 0; t < RS + 4; t++) {
        h[t % 5] = *reinterpret_cast<const float4*>(&s_h[wid * RS + t][4 * lane]);
        if (t >= 4) {
            float4 a = h[(t - 4) % 5], b2 = h[(t - 3) % 5], c = h[(t - 2) % 5];
            float4 d = h[(t - 1) % 5], e = h[t % 5];
            float4 o;
            o.x = __saturatef(tap5(a.x, b2.x, c.x, d.x, e.x));
            o.y = __saturatef(tap5(a.y, b2.y, c.y, d.y, e.y));
            o.z = __saturatef(tap5(a.z, b2.z, c.z, d.z, e.z));
            o.w = __saturatef(tap5(a.w, b2.w, c.w, d.w, e.w));
            __stcs(reinterpret_cast<float4*>(obase + (size_t)(t - 4) * Wc), o);
        }
    }
}

// ---------------------------------------------------------------------------
extern "C" void kernel_launch(void* const* d_in, const int* in_sizes, int n_in,
                              void* d_out, int out_size) {
    const float* x  = (const float*)d_in[0];
    const int*   ys = (const int*)d_in[1];
    const int*   xs = (const int*)d_in[2];
    const int*   rs = (const int*)d_in[3];
    float* out = (float*)d_out;

    // 1) clear bitmask: 2 MB / 16B = 131,072 uint4 stores
    hs_clear_mask<<<512, 256>>>();

    // 2) stamp: thread per flake
    int total_flakes = Bc * NF;                 // 251,648
    hs_stamp<<<(total_flakes + 255) / 256, 256>>>(ys, xs, rs);

    // 3) fused composite + blur + clip
    dim3 grid(Wc / TX, Hc / TY, Bc * Cc);       // (8, 16, 48)
    hs_blur<<<grid, NTHR>>>(x, out);
}